// round 1
// baseline (speedup 1.0000x reference)
#include <cuda_runtime.h>

// GraphPyramidPooling — the graph adjacency (d_in[0]) is DEAD CODE for the
// output: only the per-level sigmoid-score top-k gather/gate/scatter chain
// matters. Levels: 4096 -> 3276 -> 1965 -> 786 (Python int(k*n) semantics).

#define D   512
#define DV  (D/4)      // 128 float4 per row
#define N0  4096
#define K0  3276
#define N1  3276
#define K1  1965
#define N2  1965
#define K2  786
#define RCHUNK 512

// scratch (static device globals — no allocation allowed)
__device__ float g_s0[N0];
__device__ float g_s1[N1];
__device__ float g_s2[N2];
__device__ int   g_r0[N0];
__device__ int   g_r1[N1];
__device__ int   g_r2[N2];
__device__ float g_h1[(size_t)N1 * D];
__device__ float g_h2[(size_t)N2 * D];

__device__ __forceinline__ float warp_sum(float v) {
#pragma unroll
    for (int o = 16; o; o >>= 1) v += __shfl_xor_sync(0xffffffffu, v, o);
    return v;
}
__device__ __forceinline__ float sigmoidf(float x) {
    return 1.0f / (1.0f + expf(-x));
}

// Level-0 scores: one warp per row, s0[r] = sigmoid(h[r]·W0 + b0). Also zeroes ranks.
__global__ void scores0_kernel(const float* __restrict__ h,
                               const float* __restrict__ W,
                               const float* __restrict__ b) {
    int w    = (blockIdx.x * blockDim.x + threadIdx.x) >> 5;
    int lane = threadIdx.x & 31;
    if (w >= N0) return;
    const float4* hr = (const float4*)h + (size_t)w * DV;
    const float4* w0 = (const float4*)W;
    float acc = 0.f;
#pragma unroll
    for (int i = 0; i < 4; i++) {
        float4 a = __ldg(hr + lane + 32 * i);
        float4 c = __ldg(w0 + lane + 32 * i);
        acc += a.x * c.x + a.y * c.y + a.z * c.z + a.w * c.w;
    }
    acc = warp_sum(acc);
    if (lane == 0) {
        g_s0[w] = sigmoidf(acc + __ldg(b + 0));
        g_r0[w] = 0;
    }
}

// Exact stable-descending rank via counting (matches jax.lax.top_k ordering:
// descending value, ties broken by lower index). 2D grid: x tiles elements,
// y tiles the comparison chunk (smem, broadcast reads). atomicAdd partials.
template <int LVL>
__global__ void rank_kernel() {
    const float* s = (LVL == 0) ? g_s0 : (LVL == 1) ? g_s1 : g_s2;
    int*         r = (LVL == 0) ? g_r0 : (LVL == 1) ? g_r1 : g_r2;
    const int    n = (LVL == 0) ? N0   : (LVL == 1) ? N1   : N2;

    __shared__ float sm[RCHUNK];
    int c0 = blockIdx.y * RCHUNK;
    int nc = min(RCHUNK, n - c0);
    for (int t = threadIdx.x; t < nc; t += blockDim.x) sm[t] = s[c0 + t];
    __syncthreads();

    int i = blockIdx.x * blockDim.x + threadIdx.x;
    if (i >= n) return;
    float si = s[i];
    int jlim_eq = i - c0;  // gj < i  <=>  j < i - c0
    int cnt = 0;
#pragma unroll 8
    for (int j = 0; j < nc; j++) {
        float sj = sm[j];
        cnt += (sj > si) | ((sj == si) & (j < jlim_eq));
    }
    atomicAdd(r + i, cnt);
}

// Level-0 build: out[r] = selected ? h[r]*s0[r] : 0  (covers zero-init of out),
// h1[rank] = h[r]*s0[r], fused next-level score s1[rank] = sigmoid(row·W1+b1).
__global__ void build0_kernel(const float* __restrict__ h,
                              const float* __restrict__ W,
                              const float* __restrict__ b,
                              float* __restrict__ out) {
    int w    = (blockIdx.x * blockDim.x + threadIdx.x) >> 5;
    int lane = threadIdx.x & 31;
    if (w >= N0) return;
    int rank = g_r0[w];
    const float4* hr   = (const float4*)h + (size_t)w * DV;
    float4*       outr = (float4*)out + (size_t)w * DV;
    if (rank < K0) {
        float val = g_s0[w];
        float4*       h1r = (float4*)g_h1 + (size_t)rank * DV;
        const float4* w1  = (const float4*)W + DV;  // W row 1
        float acc = 0.f;
#pragma unroll
        for (int i = 0; i < 4; i++) {
            float4 a = __ldg(hr + lane + 32 * i);
            a.x *= val; a.y *= val; a.z *= val; a.w *= val;
            outr[lane + 32 * i] = a;
            h1r[lane + 32 * i]  = a;
            float4 c = __ldg(w1 + lane + 32 * i);
            acc += a.x * c.x + a.y * c.y + a.z * c.z + a.w * c.w;
        }
        acc = warp_sum(acc);
        if (lane == 0) {
            g_s1[rank] = sigmoidf(acc + __ldg(b + 1));
            g_r1[rank] = 0;   // every rank in [0,K0) hit exactly once
        }
    } else {
        float4 z = make_float4(0.f, 0.f, 0.f, 0.f);
#pragma unroll
        for (int i = 0; i < 4; i++) outr[lane + 32 * i] = z;
    }
}

// Level-1 build: out[p] += h1[p]*s1[p], h2[rank] = row, fused s2 matvec.
__global__ void build1_kernel(const float* __restrict__ W,
                              const float* __restrict__ b,
                              float* __restrict__ out) {
    int w    = (blockIdx.x * blockDim.x + threadIdx.x) >> 5;
    int lane = threadIdx.x & 31;
    if (w >= N1) return;
    int rank = g_r1[w];
    if (rank >= K1) return;
    float val = g_s1[w];
    const float4* h1r  = (const float4*)g_h1 + (size_t)w * DV;
    float4*       outr = (float4*)out + (size_t)w * DV;
    float4*       h2r  = (float4*)g_h2 + (size_t)rank * DV;
    const float4* w2   = (const float4*)W + 2 * DV;  // W row 2
    float acc = 0.f;
#pragma unroll
    for (int i = 0; i < 4; i++) {
        float4 a = h1r[lane + 32 * i];
        a.x *= val; a.y *= val; a.z *= val; a.w *= val;
        float4 o = outr[lane + 32 * i];
        o.x += a.x; o.y += a.y; o.z += a.z; o.w += a.w;
        outr[lane + 32 * i] = o;
        h2r[lane + 32 * i]  = a;
        float4 c = __ldg(w2 + lane + 32 * i);
        acc += a.x * c.x + a.y * c.y + a.z * c.z + a.w * c.w;
    }
    acc = warp_sum(acc);
    if (lane == 0) {
        g_s2[rank] = sigmoidf(acc + __ldg(b + 2));
        g_r2[rank] = 0;
    }
}

// Level-2 build: out[p] += h2[p]*s2[p] for selected p. No h3 materialization.
__global__ void build2_kernel(float* __restrict__ out) {
    int w    = (blockIdx.x * blockDim.x + threadIdx.x) >> 5;
    int lane = threadIdx.x & 31;
    if (w >= N2) return;
    int rank = g_r2[w];
    if (rank >= K2) return;
    float val = g_s2[w];
    const float4* h2r  = (const float4*)g_h2 + (size_t)w * DV;
    float4*       outr = (float4*)out + (size_t)w * DV;
#pragma unroll
    for (int i = 0; i < 4; i++) {
        float4 a = h2r[lane + 32 * i];
        float4 o = outr[lane + 32 * i];
        o.x += a.x * val; o.y += a.y * val; o.z += a.z * val; o.w += a.w * val;
        outr[lane + 32 * i] = o;
    }
}

extern "C" void kernel_launch(void* const* d_in, const int* in_sizes, int n_in,
                              void* d_out, int out_size) {
    // inputs: [0]=g (UNUSED), [1]=h [4096,512], [2]=W [3,512], [3]=b [3]
    const float* h = (const float*)d_in[1];
    const float* W = (const float*)d_in[2];
    const float* b = (const float*)d_in[3];
    float* out = (float*)d_out;

    scores0_kernel<<<N0 / 8, 256>>>(h, W, b);
    rank_kernel<0><<<dim3((N0 + 255) / 256, (N0 + RCHUNK - 1) / RCHUNK), 256>>>();
    build0_kernel<<<N0 / 8, 256>>>(h, W, b, out);
    rank_kernel<1><<<dim3((N1 + 255) / 256, (N1 + RCHUNK - 1) / RCHUNK), 256>>>();
    build1_kernel<<<(N1 * 32 + 255) / 256, 256>>>(W, b, out);
    rank_kernel<2><<<dim3((N2 + 255) / 256, (N2 + RCHUNK - 1) / RCHUNK), 256>>>();
    build2_kernel<<<(N2 * 32 + 255) / 256, 256>>>(out);
}

// round 2
// speedup vs baseline: 1.3509x; 1.3509x over previous
#include <cuda_runtime.h>

// GraphPyramidPooling — adjacency (d_in[0]) is dead code for the output.
// Live path: per-level sigmoid scores -> exact stable top-k rank -> gather/
// gate/scatter. Levels: 4096 -> 3276 -> 1965 -> 786.
//
// R1 change: rank kernels restructured for full-chip occupancy (fine j-chunks,
// 256-512 blocks/level) + region-split inner loops that drop the tie-index
// compare for all non-diagonal blocks:
//   rank(i) = #{j<i : s_j >= s_i} + #{j>i : s_j > s_i}

#define D   512
#define DV  (D/4)
#define N0  4096
#define K0  3276
#define N1  3276
#define K1  1965
#define N2  1965
#define K2  786

__device__ float g_s0[N0];
__device__ float g_s1[N1];
__device__ float g_s2[N2];
__device__ int   g_r0[N0];
__device__ int   g_r1[N1];
__device__ int   g_r2[N2];
__device__ float g_h1[(size_t)N1 * D];
__device__ float g_h2[(size_t)N2 * D];

__device__ __forceinline__ float warp_sum(float v) {
#pragma unroll
    for (int o = 16; o; o >>= 1) v += __shfl_xor_sync(0xffffffffu, v, o);
    return v;
}
__device__ __forceinline__ float sigmoidf(float x) {
    return 1.0f / (1.0f + expf(-x));
}

// Level-0 scores: one warp per row. Also zeroes g_r0.
__global__ void scores0_kernel(const float* __restrict__ h,
                               const float* __restrict__ W,
                               const float* __restrict__ b) {
    int w    = (blockIdx.x * blockDim.x + threadIdx.x) >> 5;
    int lane = threadIdx.x & 31;
    if (w >= N0) return;
    const float4* hr = (const float4*)h + (size_t)w * DV;
    const float4* w0 = (const float4*)W;
    float acc = 0.f;
#pragma unroll
    for (int i = 0; i < 4; i++) {
        float4 a = __ldg(hr + lane + 32 * i);
        float4 c = __ldg(w0 + lane + 32 * i);
        acc += a.x * c.x + a.y * c.y + a.z * c.z + a.w * c.w;
    }
    acc = warp_sum(acc);
    if (lane == 0) {
        g_s0[w] = sigmoidf(acc + __ldg(b + 0));
        g_r0[w] = 0;
    }
}

// Exact stable-descending rank via tiled counting.
// Block = TPB i's (x) vs CH j's (y, staged through smem). Non-diagonal blocks
// use a single float compare per j; diagonal blocks (chunk overlaps i-tile)
// fall back to the full tie-break comparator.
template <int LVL, int CH, int TPB>
__global__ void rank_kernel() {
    const float* s = (LVL == 0) ? g_s0 : (LVL == 1) ? g_s1 : g_s2;
    int*         r = (LVL == 0) ? g_r0 : (LVL == 1) ? g_r1 : g_r2;
    const int    n = (LVL == 0) ? N0   : (LVL == 1) ? N1   : N2;

    __shared__ float sm[CH];
    const int c0 = blockIdx.y * CH;
    const int nc = min(CH, n - c0);
    const int i0 = blockIdx.x * TPB;

    for (int t = threadIdx.x; t < nc; t += TPB) sm[t] = s[c0 + t];
    __syncthreads();

    const int i = i0 + threadIdx.x;
    if (i >= n) return;
    const float si = s[i];
    int cnt = 0;
    const float4* sm4 = (const float4*)sm;
    const int nc4 = nc >> 2;

    if (c0 + nc <= i0) {
        // every j in chunk has j < i : count s_j >= s_i
#pragma unroll 8
        for (int q = 0; q < nc4; q++) {
            float4 v = sm4[q];
            cnt += (v.x >= si) + (v.y >= si) + (v.z >= si) + (v.w >= si);
        }
        for (int j = nc4 * 4; j < nc; j++) cnt += (sm[j] >= si);
    } else if (c0 >= i0 + TPB) {
        // every j in chunk has j > i : count s_j > s_i
#pragma unroll 8
        for (int q = 0; q < nc4; q++) {
            float4 v = sm4[q];
            cnt += (v.x > si) + (v.y > si) + (v.z > si) + (v.w > si);
        }
        for (int j = nc4 * 4; j < nc; j++) cnt += (sm[j] > si);
    } else {
        // diagonal block: full stable comparator
        for (int j = 0; j < nc; j++) {
            float sj = sm[j];
            int   gj = c0 + j;
            cnt += (sj > si) | ((sj == si) & (gj < i));
        }
    }
    if (cnt) atomicAdd(r + i, cnt);
}

// Level-0 build: out[r] = selected ? h[r]*s : 0 (covers poison), scatter to
// h1[rank], fused next-level matvec for s1. Zeroes g_r1 slots it owns.
__global__ void build0_kernel(const float* __restrict__ h,
                              const float* __restrict__ W,
                              const float* __restrict__ b,
                              float* __restrict__ out) {
    int w    = (blockIdx.x * blockDim.x + threadIdx.x) >> 5;
    int lane = threadIdx.x & 31;
    if (w >= N0) return;
    int rank = g_r0[w];
    const float4* hr   = (const float4*)h + (size_t)w * DV;
    float4*       outr = (float4*)out + (size_t)w * DV;
    if (rank < K0) {
        float val = g_s0[w];
        float4*       h1r = (float4*)g_h1 + (size_t)rank * DV;
        const float4* w1  = (const float4*)W + DV;
        float acc = 0.f;
#pragma unroll
        for (int i = 0; i < 4; i++) {
            float4 a = __ldg(hr + lane + 32 * i);
            a.x *= val; a.y *= val; a.z *= val; a.w *= val;
            outr[lane + 32 * i] = a;
            h1r[lane + 32 * i]  = a;
            float4 c = __ldg(w1 + lane + 32 * i);
            acc += a.x * c.x + a.y * c.y + a.z * c.z + a.w * c.w;
        }
        acc = warp_sum(acc);
        if (lane == 0) {
            g_s1[rank] = sigmoidf(acc + __ldg(b + 1));
            g_r1[rank] = 0;
        }
    } else {
        float4 z = make_float4(0.f, 0.f, 0.f, 0.f);
#pragma unroll
        for (int i = 0; i < 4; i++) outr[lane + 32 * i] = z;
    }
}

// Level-1 build: out[p] += h1[p]*s1[p], scatter h2[rank], fused s2 matvec.
__global__ void build1_kernel(const float* __restrict__ W,
                              const float* __restrict__ b,
                              float* __restrict__ out) {
    int w    = (blockIdx.x * blockDim.x + threadIdx.x) >> 5;
    int lane = threadIdx.x & 31;
    if (w >= N1) return;
    int rank = g_r1[w];
    if (rank >= K1) return;
    float val = g_s1[w];
    const float4* h1r  = (const float4*)g_h1 + (size_t)w * DV;
    float4*       outr = (float4*)out + (size_t)w * DV;
    float4*       h2r  = (float4*)g_h2 + (size_t)rank * DV;
    const float4* w2   = (const float4*)W + 2 * DV;
    float acc = 0.f;
#pragma unroll
    for (int i = 0; i < 4; i++) {
        float4 a = h1r[lane + 32 * i];
        a.x *= val; a.y *= val; a.z *= val; a.w *= val;
        float4 o = outr[lane + 32 * i];
        o.x += a.x; o.y += a.y; o.z += a.z; o.w += a.w;
        outr[lane + 32 * i] = o;
        h2r[lane + 32 * i]  = a;
        float4 c = __ldg(w2 + lane + 32 * i);
        acc += a.x * c.x + a.y * c.y + a.z * c.z + a.w * c.w;
    }
    acc = warp_sum(acc);
    if (lane == 0) {
        g_s2[rank] = sigmoidf(acc + __ldg(b + 2));
        g_r2[rank] = 0;
    }
}

// Level-2 build: out[p] += h2[p]*s2[p] for selected p.
__global__ void build2_kernel(float* __restrict__ out) {
    int w    = (blockIdx.x * blockDim.x + threadIdx.x) >> 5;
    int lane = threadIdx.x & 31;
    if (w >= N2) return;
    int rank = g_r2[w];
    if (rank >= K2) return;
    float val = g_s2[w];
    const float4* h2r  = (const float4*)g_h2 + (size_t)w * DV;
    float4*       outr = (float4*)out + (size_t)w * DV;
#pragma unroll
    for (int i = 0; i < 4; i++) {
        float4 a = h2r[lane + 32 * i];
        float4 o = outr[lane + 32 * i];
        o.x += a.x * val; o.y += a.y * val; o.z += a.z * val; o.w += a.w * val;
        outr[lane + 32 * i] = o;
    }
}

extern "C" void kernel_launch(void* const* d_in, const int* in_sizes, int n_in,
                              void* d_out, int out_size) {
    // inputs: [0]=g (UNUSED), [1]=h [4096,512], [2]=W [3,512], [3]=b [3]
    const float* h = (const float*)d_in[1];
    const float* W = (const float*)d_in[2];
    const float* b = (const float*)d_in[3];
    float* out = (float*)d_out;

    scores0_kernel<<<N0 / 8, 256>>>(h, W, b);

    // rank0: 16 x 16 = 256 blocks
    rank_kernel<0, 256, 256><<<dim3((N0 + 255) / 256, (N0 + 255) / 256), 256>>>();
    build0_kernel<<<N0 / 8, 256>>>(h, W, b, out);

    // rank1: 13 x 26 = 338 blocks
    rank_kernel<1, 128, 256><<<dim3((N1 + 255) / 256, (N1 + 127) / 128), 256>>>();
    build1_kernel<<<(N1 * 32 + 255) / 256, 256>>>(W, b, out);

    // rank2: 16 x 16 = 256 blocks (128-thread i-tiles)
    rank_kernel<2, 128, 128><<<dim3((N2 + 127) / 128, (N2 + 127) / 128), 128>>>();
    build2_kernel<<<(N2 * 32 + 255) / 256, 256>>>(out);
}